// round 15
// baseline (speedup 1.0000x reference)
#include <cuda_runtime.h>
#include <math.h>

#define Bk 2
#define Tk 128
#define Dk 384
#define Nk (Bk*Tk)        // 256 token rows
#define Hk 1024
#define Ck 256
#define NITER 4
#define PADk (Dk-1)       // 383
#define Sk (2*Dk-1)       // 767 shifts
#define EPSk 1e-6f
#define TEMPERk 10.0f
#define MASKVAL 1e-10f
#define FULLMASK 0xffffffffu

// ---------------- scratch (no allocations allowed) ----------------
__device__ float  g_xele[Nk*Dk];
__device__ float  g_h[Nk*Hk];
__device__ float  g_partial[NITER*Nk];
__device__ float  g_cnt[Nk];          // per-row count(y!=0)
__device__ int    g_ctr = 0;

// orderable key: larger float -> larger unsigned
__device__ __forceinline__ unsigned fkey(float f) {
    unsigned u = __float_as_uint(f);
    return (u & 0x80000000u) ? ~u : (u | 0x80000000u);
}

// ---- block reductions for 384 threads (12 warps) ----
__device__ __forceinline__ float brsum(float v, float* sw) {
    int t = threadIdx.x;
    #pragma unroll
    for (int o = 16; o > 0; o >>= 1) v += __shfl_down_sync(FULLMASK, v, o);
    if ((t & 31) == 0) sw[t >> 5] = v;
    __syncthreads();
    if (t < 32) {
        float x = (t < 12) ? sw[t] : 0.f;
        #pragma unroll
        for (int o = 16; o > 0; o >>= 1) x += __shfl_down_sync(FULLMASK, x, o);
        if (t == 0) sw[0] = x;
    }
    __syncthreads();
    float r = sw[0];
    __syncthreads();
    return r;
}
__device__ __forceinline__ float brmax(float v, float* sw) {
    int t = threadIdx.x;
    #pragma unroll
    for (int o = 16; o > 0; o >>= 1) v = fmaxf(v, __shfl_down_sync(FULLMASK, v, o));
    if ((t & 31) == 0) sw[t >> 5] = v;
    __syncthreads();
    if (t < 32) {
        float x = (t < 12) ? sw[t] : -INFINITY;
        #pragma unroll
        for (int o = 16; o > 0; o >>= 1) x = fmaxf(x, __shfl_down_sync(FULLMASK, x, o));
        if (t == 0) sw[0] = x;
    }
    __syncthreads();
    float r = sw[0];
    __syncthreads();
    return r;
}
__device__ __forceinline__ int brargmax(float v, int idx, float* sw, int* si) {
    int t = threadIdx.x;
    #pragma unroll
    for (int o = 16; o > 0; o >>= 1) {
        float vo = __shfl_down_sync(FULLMASK, v, o);
        int   io = __shfl_down_sync(FULLMASK, idx, o);
        if (vo > v || (vo == v && io < idx)) { v = vo; idx = io; }
    }
    if ((t & 31) == 0) { sw[t >> 5] = v; si[t >> 5] = idx; }
    __syncthreads();
    if (t < 32) {
        float x = (t < 12) ? sw[t] : -INFINITY;
        int   i = (t < 12) ? si[t] : 0x7fffffff;
        #pragma unroll
        for (int o = 16; o > 0; o >>= 1) {
            float vo = __shfl_down_sync(FULLMASK, x, o);
            int   io = __shfl_down_sync(FULLMASK, i, o);
            if (vo > x || (vo == x && io < i)) { x = vo; i = io; }
        }
        if (t == 0) si[0] = i;
    }
    __syncthreads();
    int r = si[0];
    __syncthreads();
    return r;
}

// ================= kernel 1: shift/argmax/attn -> x_ele + denom partials =================
// shift tile: 96 octs (8 shifts) x 4 u-quarters (96 u's, 24 steps)
__global__ __launch_bounds__(384) void k_xele(const float* __restrict__ x,
                                              const float* __restrict__ y) {
    int row = blockIdx.x;
    int t = threadIdx.x;
    __shared__ __align__(16) float xp[1168];   // zero-padded: xp[i] = x[i-383]; +16 pad for prefetch
    __shared__ __align__(16) float ys[Dk];
    __shared__ float xa[Dk];
    __shared__ float PS[Dk + 1];
    __shared__ float dpS[4][96][8];            // [quarter][oct][shift-in-oct]
    __shared__ float sw[12];
    __shared__ int   si[12];

    const float* xr = x + (size_t)row * Dk;
    const float* yr = y + (size_t)row * Dk;
    xp[t] = 0.f; xp[t + 384] = 0.f; xp[t + 768] = 0.f;
    if (t < 16) xp[1152 + t] = 0.f;
    float yv_t = yr[t];
    ys[t] = yv_t;
    __syncthreads();
    float xv_t = xr[t];
    xp[PADk + t] = xv_t;

    // prefix sums of x^2 : PS[u] = sum_{v<u} x[v]^2
    {
        float x2 = xv_t * xv_t;
        float incl = x2;
        #pragma unroll
        for (int o = 1; o < 32; o <<= 1) {
            float vv = __shfl_up_sync(FULLMASK, incl, o);
            if ((t & 31) >= o) incl += vv;
        }
        if ((t & 31) == 31) sw[t >> 5] = incl;
        __syncthreads();
        if (t < 32) {
            float wv = (t < 12) ? sw[t] : 0.f;
            float wi = wv;
            #pragma unroll
            for (int o = 1; o < 32; o <<= 1) {
                float vv = __shfl_up_sync(FULLMASK, wi, o);
                if (t >= o) wi += vv;
            }
            if (t < 12) sw[t] = wi - wv;   // exclusive warp offsets
        }
        __syncthreads();
        PS[t + 1] = incl + sw[t >> 5];
        if (t == 0) PS[0] = 0.f;
        __syncthreads();
    }

    float qn = sqrtf(brsum(yv_t * yv_t, sw));
    float cn = brsum((yv_t != 0.0f) ? 1.f : 0.f, sw);
    if (t == 0) g_cnt[row] = cn;

    // shift phase: oct oc (8 shifts at s0=8*oc), u-quarter qt
    {
        int oc = t % 96, qt = t / 96;
        int s0 = 8 * oc;
        int ub = qt * 96;
        float d0 = 0.f, d1 = 0.f, d2 = 0.f, d3 = 0.f;
        float d4 = 0.f, d5 = 0.f, d6 = 0.f, d7 = 0.f;
        const float4* xp4 = (const float4*)xp;
        const float4* ys4 = (const float4*)ys;
        int base = (s0 + ub) >> 2;
        int yb = ub >> 2;
        float4 c0 = xp4[base], c1 = xp4[base + 1], c2 = xp4[base + 2];
        #pragma unroll 4
        for (int st = 0; st < 24; ++st) {
            float4 yv = ys4[yb + st];
            float w0 = c0.x, w1 = c0.y, w2 = c0.z, w3 = c0.w;
            float w4 = c1.x, w5 = c1.y, w6 = c1.z, w7 = c1.w;
            float w8 = c2.x, w9 = c2.y, wA = c2.z;
            d0 += w0 * yv.x + w1 * yv.y + w2 * yv.z + w3 * yv.w;
            d1 += w1 * yv.x + w2 * yv.y + w3 * yv.z + w4 * yv.w;
            d2 += w2 * yv.x + w3 * yv.y + w4 * yv.z + w5 * yv.w;
            d3 += w3 * yv.x + w4 * yv.y + w5 * yv.z + w6 * yv.w;
            d4 += w4 * yv.x + w5 * yv.y + w6 * yv.z + w7 * yv.w;
            d5 += w5 * yv.x + w6 * yv.y + w7 * yv.z + w8 * yv.w;
            d6 += w6 * yv.x + w7 * yv.y + w8 * yv.z + w9 * yv.w;
            d7 += w7 * yv.x + w8 * yv.y + w9 * yv.z + wA * yv.w;
            c0 = c1; c1 = c2; c2 = xp4[base + st + 3];
        }
        float* dp = dpS[qt][oc];
        dp[0] = d0; dp[1] = d1; dp[2] = d2; dp[3] = d3;
        dp[4] = d4; dp[5] = d5; dp[6] = d6; dp[7] = d7;
    }
    __syncthreads();

    float bv = -INFINITY; int bi = 0x7fffffff;
    if (t < 96) {
        int s0 = 8 * t;
        float dots[8];
        #pragma unroll
        for (int q = 0; q < 8; ++q)
            dots[q] = dpS[0][t][q] + dpS[1][t][q] + dpS[2][t][q] + dpS[3][t][q];
        #pragma unroll
        for (int q = 0; q < 8; ++q) {
            int s = s0 + q;
            if (s < Sk) {
                int hi = (s < Dk - 1 ? s : Dk - 1) + 1;
                int lo = (s - PADk > 0) ? (s - PADk) : 0;
                float ss = PS[hi] - PS[lo];
                float sim = dots[q] / (qn * sqrtf(ss) + EPSk);
                if (isnan(sim)) sim = 0.f;
                if (sim > bv) { bv = sim; bi = s; }   // ascending q keeps first index on tie
            }
        }
    }
    int theta = brargmax(bv, bi, sw, si);

    float v = xp[t + theta];
    float no = brsum(v * v, sw);
    float dn = sqrtf(no) * qn + EPSk;

    float z = (v * yv_t / dn) / TEMPERk;
    float m = brmax(z, sw);
    float e = expf(z - m);
    float ssum = brsum(e, sw);
    xa[t] = v * e / ssum;
    __syncthreads();

    int shift = theta - PADk;
    int u = t - shift;
    g_xele[(size_t)row * Dk + t] = (u >= 0 && u < Dk) ? xa[u] : 0.f;
}

// ================= kernel 2: h = x_ele @ W_enc + b_enc =================
// grid 256 = 32 rowgroups(8 rows) x 8 colgroups(128 cols), 128 threads, 1 col/thread
__global__ __launch_bounds__(128) void k_enc(const float* __restrict__ We,
                                             const float* __restrict__ be) {
    int rg = blockIdx.x >> 3;
    int cg = blockIdx.x & 7;
    int t  = threadIdx.x;
    int col = cg * 128 + t;
    __shared__ __align__(16) float xs[8 * Dk];
    for (int i = t; i < 8 * Dk; i += 128) xs[i] = g_xele[(size_t)rg * 8 * Dk + i];
    __syncthreads();

    float acc[8];
    float b = be[col];
    #pragma unroll
    for (int r = 0; r < 8; ++r) acc[r] = b;

    for (int k = 0; k < Dk; k += 4) {
        float w0 = We[(size_t)(k + 0) * Hk + col];
        float w1 = We[(size_t)(k + 1) * Hk + col];
        float w2 = We[(size_t)(k + 2) * Hk + col];
        float w3 = We[(size_t)(k + 3) * Hk + col];
        #pragma unroll
        for (int r = 0; r < 8; ++r) {
            float4 xv = *(const float4*)&xs[r * Dk + k];
            acc[r] += xv.x * w0;
            acc[r] += xv.y * w1;
            acc[r] += xv.z * w2;
            acc[r] += xv.w * w3;
        }
    }
    #pragma unroll
    for (int r = 0; r < 8; ++r)
        g_h[(size_t)(rg * 8 + r) * Hk + col] = acc[r];
}

// ===== kernel 3 (fused): 4x top-256 (radix + shortcut) -> union decode -> loss =====
// one block per row, 384 threads  (R6/R9-proven structure)
__global__ __launch_bounds__(384) void k_seldec(const float* __restrict__ Wd,
                                                const float* __restrict__ bd,
                                                const float* __restrict__ x,
                                                const float* __restrict__ y,
                                                float* __restrict__ out,
                                                float* __restrict__ losses) {
    int row = blockIdx.x;
    int t = threadIdx.x;
    int lane = t & 31;

    __shared__ float    hs[Hk];
    __shared__ unsigned kv[Hk];
    __shared__ int      selhist[Hk];
    __shared__ int      sil[Hk];          // union row offsets (j*Dk)
    __shared__ float4   svl[Hk];          // per-union values for 4 iters
    __shared__ int      cnt[256];
    __shared__ int      sc[256];
    __shared__ float4   s4[12];
    __shared__ unsigned sh_prefix;
    __shared__ int      sh_k, sh_done, sh_ngnm, sh_U, slast;

    const unsigned MASKKEY = fkey(MASKVAL);

    const float* hr = g_h + (size_t)row * Hk;
    if (t < 256) {
        float4 h4 = *(const float4*)&hr[t * 4];
        hs[t*4+0] = h4.x; hs[t*4+1] = h4.y; hs[t*4+2] = h4.z; hs[t*4+3] = h4.w;
        kv[t*4+0] = fkey(h4.x); kv[t*4+1] = fkey(h4.y);
        kv[t*4+2] = fkey(h4.z); kv[t*4+3] = fkey(h4.w);
        selhist[t*4+0] = 0; selhist[t*4+1] = 0; selhist[t*4+2] = 0; selhist[t*4+3] = 0;
    }
    __syncthreads();

    // ---- 4 dependent top-k selections ----
    for (int it = 0; it < NITER; ++it) {
        unsigned Tkey; int k; unsigned pmaskF;
        int shortcut = 0;

        if (it > 0) {
            int packed = 0;
            if (t < 256) {
                int ng = 0, nm = 0;
                #pragma unroll
                for (int q = 0; q < 4; ++q) {
                    unsigned u = kv[t * 4 + q];
                    ng += (u > MASKKEY);
                    nm += (u == MASKKEY);
                }
                packed = (ng << 16) | nm;
            }
            #pragma unroll
            for (int o = 16; o > 0; o >>= 1) packed += __shfl_down_sync(FULLMASK, packed, o);
            if (lane == 0) sc[t >> 5] = packed;
            __syncthreads();
            if (t < 32) {
                int v = (t < 8) ? sc[t] : 0;
                #pragma unroll
                for (int o = 4; o > 0; o >>= 1) v += __shfl_down_sync(FULLMASK, v, o);
                if (t == 0) sh_ngnm = v;
            }
            __syncthreads();
            int ngT = sh_ngnm >> 16, nmT = sh_ngnm & 0xffff;
            if (ngT <= Ck && Ck <= ngT + nmT) {
                Tkey = MASKKEY; k = Ck - ngT; pmaskF = FULLMASK;
                shortcut = 1;
            }
            __syncthreads();
        }

        if (!shortcut) {
            if (t == 0) { sh_prefix = 0; sh_k = Ck; sh_done = 0; }
            __syncthreads();
            unsigned pmask = 0;
            for (int sb = 24; sb >= 0; sb -= 8) {
                if (sh_done) break;
                unsigned prefix = sh_prefix;
                if (t < 256) cnt[t] = 0;
                __syncthreads();
                #pragma unroll
                for (int ch = 0; ch < 3; ++ch) {
                    int i = t + ch * 384;
                    int bucket = -1;
                    if (i < Hk) {
                        unsigned u = kv[i];
                        if ((u & pmask) == prefix) bucket = (int)((u >> sb) & 0xffu);
                    }
                    unsigned same = __match_any_sync(FULLMASK, bucket);
                    if (bucket >= 0 && lane == (__ffs(same) - 1))
                        atomicAdd(&cnt[bucket], __popc(same));
                }
                __syncthreads();
                if (t < 32) {
                    int kk = sh_k;
                    int base = t * 8;
                    int c[8], s[8];
                    #pragma unroll
                    for (int q = 0; q < 8; ++q) c[q] = cnt[base + q];
                    s[7] = c[7];
                    #pragma unroll
                    for (int q = 6; q >= 0; --q) s[q] = s[q + 1] + c[q];
                    int tot = s[0];
                    int suf = tot;
                    #pragma unroll
                    for (int o = 1; o < 32; o <<= 1) {
                        int vv = __shfl_down_sync(FULLMASK, suf, o);
                        if (t + o < 32) suf += vv;
                    }
                    int basev = suf - tot;   // suffix over lanes > t
                    #pragma unroll
                    for (int q = 0; q < 8; ++q) {
                        int sq = basev + s[q];
                        int sn = (q < 7) ? basev + s[q + 1] : basev;
                        if (sq >= kk && sn < kk) {
                            sh_prefix = prefix | ((unsigned)(base + q) << sb);
                            sh_k = kk - sn;
                            if (sq == kk) sh_done = 1;
                        }
                    }
                }
                pmask |= (0xffu << sb);
                __syncthreads();
            }
            Tkey = sh_prefix; k = sh_k; pmaskF = pmask;
        }

        // tie-break by ascending index; thread t<256 owns elems [4t, 4t+4)
        int eq[4], gt_[4]; int eqc = 0;
        if (t < 256) {
            #pragma unroll
            for (int q = 0; q < 4; ++q) {
                unsigned u = kv[t * 4 + q] & pmaskF;
                eq[q]  = (u == Tkey);
                gt_[q] = (u >  Tkey);
                eqc += eq[q];
            }
            sc[t] = eqc;
        }
        __syncthreads();
        if (t < 32) {
            int base = t * 8;
            int v[8], inc[8];
            int run = 0;
            #pragma unroll
            for (int q = 0; q < 8; ++q) { v[q] = sc[base + q]; run += v[q]; inc[q] = run; }
            int tot = run, pre = tot;
            #pragma unroll
            for (int o = 1; o < 32; o <<= 1) {
                int vv = __shfl_up_sync(FULLMASK, pre, o);
                if (t >= o) pre += vv;
            }
            int basev = pre - tot;
            #pragma unroll
            for (int q = 0; q < 8; ++q) sc[base + q] = basev + inc[q] - v[q];
        }
        __syncthreads();
        if (t < 256) {
            int eqbase = sc[t];
            int le = 0;
            #pragma unroll
            for (int q = 0; q < 4; ++q) {
                int j = t * 4 + q;
                int sel = gt_[q] || (eq[q] && (eqbase + le) < k);
                le += eq[q];
                if (sel) { selhist[j] |= (1 << it); kv[j] = MASKKEY; }
            }
        }
        __syncthreads();
    }

    // ---- union compaction + per-iter value build (in smem) ----
    int uc = 0;
    if (t < 256) {
        #pragma unroll
        for (int q = 0; q < 4; ++q) uc += (selhist[t * 4 + q] != 0);
        sc[t] = uc;
    }
    __syncthreads();
    if (t < 32) {
        int base = t * 8;
        int v[8], inc[8];
        int run = 0;
        #pragma unroll
        for (int q = 0; q < 8; ++q) { v[q] = sc[base + q]; run += v[q]; inc[q] = run; }
        int tot = run, pre = tot;
        #pragma unroll
        for (int o = 1; o < 32; o <<= 1) {
            int vv = __shfl_up_sync(FULLMASK, pre, o);
            if (t >= o) pre += vv;
        }
        int basev = pre - tot;
        #pragma unroll
        for (int q = 0; q < 8; ++q) sc[base + q] = basev + inc[q] - v[q];
        if (t == 31) sh_U = basev + inc[7];
    }
    __syncthreads();
    if (t < 256) {
        int p = sc[t];
        #pragma unroll
        for (int q = 0; q < 4; ++q) {
            int j = t * 4 + q;
            int s = selhist[j];
            if (s) {
                float hv_ = hs[j];
                float4 v;
                v.x = (s & 1) ?  hv_ : 0.f;
                v.y = (s & 2) ? ((s & 1) ? MASKVAL : hv_) : 0.f;
                v.z = (s & 4) ? ((s & 3) ? MASKVAL : hv_) : 0.f;
                v.w = (s & 8) ? ((s & 7) ? MASKVAL : hv_) : 0.f;
                sil[p] = j * Dk;
                svl[p] = v;
                ++p;
            }
        }
    }
    __syncthreads();
    int U = sh_U;
    int Upad = (U + 7) & ~7;
    if (t < Upad - U) {
        float4 z; z.x = z.y = z.z = z.w = 0.f;
        sil[U + t] = 0;
        svl[U + t] = z;
    }
    __syncthreads();

    // ---- decode: thread t owns output column t for all 4 iters; unroll 8 ----
    float bdt = bd[t];
    float a0 = bdt, a1 = bdt, a2 = bdt, a3 = bdt;
    const float* Wt = Wd + t;
    for (int i = 0; i < Upad; i += 8) {
        int j0 = sil[i],   j1 = sil[i+1], j2 = sil[i+2], j3 = sil[i+3];
        int j4 = sil[i+4], j5 = sil[i+5], j6 = sil[i+6], j7 = sil[i+7];
        float w0 = Wt[j0], w1 = Wt[j1], w2 = Wt[j2], w3 = Wt[j3];
        float w4 = Wt[j4], w5 = Wt[j5], w6 = Wt[j6], w7 = Wt[j7];
        float4 v0 = svl[i],   v1 = svl[i+1], v2 = svl[i+2], v3 = svl[i+3];
        float4 v4 = svl[i+4], v5 = svl[i+5], v6 = svl[i+6], v7 = svl[i+7];
        a0 += v0.x * w0; a1 += v0.y * w0; a2 += v0.z * w0; a3 += v0.w * w0;
        a0 += v1.x * w1; a1 += v1.y * w1; a2 += v1.z * w1; a3 += v1.w * w1;
        a0 += v2.x * w2; a1 += v2.y * w2; a2 += v2.z * w2; a3 += v2.w * w2;
        a0 += v3.x * w3; a1 += v3.y * w3; a2 += v3.z * w3; a3 += v3.w * w3;
        a0 += v4.x * w4; a1 += v4.y * w4; a2 += v4.z * w4; a3 += v4.w * w4;
        a0 += v5.x * w5; a1 += v5.y * w5; a2 += v5.z * w5; a3 += v5.w * w5;
        a0 += v6.x * w6; a1 += v6.y * w6; a2 += v6.z * w6; a3 += v6.w * w6;
        a0 += v7.x * w7; a1 += v7.y * w7; a2 += v7.z * w7; a3 += v7.w * w7;
    }

    // ---- outputs + masked-MSE partials ----
    float xv = x[(size_t)row * Dk + t];
    float yv = y[(size_t)row * Dk + t];
    out[((size_t)0 * Nk + row) * Dk + t] = a0;
    out[((size_t)1 * Nk + row) * Dk + t] = a1;
    out[((size_t)2 * Nk + row) * Dk + t] = a2;
    out[((size_t)3 * Nk + row) * Dk + t] = a3;

    float4 d;
    if (yv != 0.0f) {
        float e0 = a0 - xv, e1 = a1 - xv, e2 = a2 - xv, e3 = a3 - xv;
        d.x = e0 * e0; d.y = e1 * e1; d.z = e2 * e2; d.w = e3 * e3;
    } else {
        d.x = d.y = d.z = d.w = 0.f;
    }
    #pragma unroll
    for (int o = 16; o > 0; o >>= 1) {
        d.x += __shfl_down_sync(FULLMASK, d.x, o);
        d.y += __shfl_down_sync(FULLMASK, d.y, o);
        d.z += __shfl_down_sync(FULLMASK, d.z, o);
        d.w += __shfl_down_sync(FULLMASK, d.w, o);
    }
    if (lane == 0) s4[t >> 5] = d;
    __syncthreads();
    if (t < 32) {
        float4 v;
        if (t < 12) v = s4[t];
        else { v.x = v.y = v.z = v.w = 0.f; }
        #pragma unroll
        for (int o = 16; o > 0; o >>= 1) {
            v.x += __shfl_down_sync(FULLMASK, v.x, o);
            v.y += __shfl_down_sync(FULLMASK, v.y, o);
            v.z += __shfl_down_sync(FULLMASK, v.z, o);
            v.w += __shfl_down_sync(FULLMASK, v.w, o);
        }
        if (t == 0) {
            g_partial[0 * Nk + row] = v.x;
            g_partial[1 * Nk + row] = v.y;
            g_partial[2 * Nk + row] = v.z;
            g_partial[3 * Nk + row] = v.w;
        }
    }
    __threadfence();
    if (t == 0) slast = (atomicAdd(&g_ctr, 1) == Nk - 1);
    __syncthreads();

    if (slast) {
        __shared__ float s_num[4];
        __shared__ float s_den;
        if (t < 128) {
            int w = t >> 5, l = t & 31;
            float s = 0.f;
            for (int j = l; j < Nk; j += 32) s += ((volatile float*)g_partial)[w * Nk + j];
            #pragma unroll
            for (int o = 16; o > 0; o >>= 1) s += __shfl_down_sync(FULLMASK, s, o);
            if (l == 0) s_num[w] = s;
        } else if (t < 160) {
            int l = t - 128;
            float dsum = 0.f;
            for (int j = l; j < Nk; j += 32) dsum += g_cnt[j];
            #pragma unroll
            for (int o = 16; o > 0; o >>= 1) dsum += __shfl_down_sync(FULLMASK, dsum, o);
            if (l == 0) s_den = dsum;
        }
        __syncthreads();
        if (t < 4) losses[t] = s_num[t] / s_den;
        if (t == 0) g_ctr = 0;   // reset for next graph replay
    }
}

extern "C" void kernel_launch(void* const* d_in, const int* in_sizes, int n_in,
                              void* d_out, int out_size) {
    const float* x  = (const float*)d_in[0];
    const float* y  = (const float*)d_in[1];
    const float* We = (const float*)d_in[2];
    const float* be = (const float*)d_in[3];
    const float* Wd = (const float*)d_in[4];
    const float* bd = (const float*)d_in[5];
    float* out = (float*)d_out;
    float* losses = out + (out_size - NITER);

    k_xele<<<Nk, 384>>>(x, y);
    k_enc<<<256, 128>>>(We, be);
    k_seldec<<<Nk, 384>>>(Wd, bd, x, y, out, losses);
}

// round 16
// speedup vs baseline: 1.0245x; 1.0245x over previous
#include <cuda_runtime.h>
#include <math.h>

#define Bk 2
#define Tk 128
#define Dk 384
#define Nk (Bk*Tk)        // 256 token rows
#define Hk 1024
#define Ck 256
#define NITER 4
#define PADk (Dk-1)       // 383
#define Sk (2*Dk-1)       // 767 shifts
#define EPSk 1e-6f
#define TEMPERk 10.0f
#define MASKVAL 1e-10f
#define FULLMASK 0xffffffffu

#define GDC_WAIT()   asm volatile("griddepcontrol.wait;" ::: "memory")
#define GDC_LAUNCH() asm volatile("griddepcontrol.launch_dependents;" ::: "memory")

// ---------------- scratch (no allocations allowed) ----------------
__device__ float  g_xele[Nk*Dk];
__device__ float  g_h[Nk*Hk];
__device__ float  g_partial[NITER*Nk];
__device__ float  g_cnt[Nk];          // per-row count(y!=0)
__device__ int    g_ctr = 0;

// orderable key: larger float -> larger unsigned
__device__ __forceinline__ unsigned fkey(float f) {
    unsigned u = __float_as_uint(f);
    return (u & 0x80000000u) ? ~u : (u | 0x80000000u);
}

// ---- block reductions for 384 threads (12 warps) ----
__device__ __forceinline__ float brsum(float v, float* sw) {
    int t = threadIdx.x;
    #pragma unroll
    for (int o = 16; o > 0; o >>= 1) v += __shfl_down_sync(FULLMASK, v, o);
    if ((t & 31) == 0) sw[t >> 5] = v;
    __syncthreads();
    if (t < 32) {
        float x = (t < 12) ? sw[t] : 0.f;
        #pragma unroll
        for (int o = 16; o > 0; o >>= 1) x += __shfl_down_sync(FULLMASK, x, o);
        if (t == 0) sw[0] = x;
    }
    __syncthreads();
    float r = sw[0];
    __syncthreads();
    return r;
}
__device__ __forceinline__ float brmax(float v, float* sw) {
    int t = threadIdx.x;
    #pragma unroll
    for (int o = 16; o > 0; o >>= 1) v = fmaxf(v, __shfl_down_sync(FULLMASK, v, o));
    if ((t & 31) == 0) sw[t >> 5] = v;
    __syncthreads();
    if (t < 32) {
        float x = (t < 12) ? sw[t] : -INFINITY;
        #pragma unroll
        for (int o = 16; o > 0; o >>= 1) x = fmaxf(x, __shfl_down_sync(FULLMASK, x, o));
        if (t == 0) sw[0] = x;
    }
    __syncthreads();
    float r = sw[0];
    __syncthreads();
    return r;
}
__device__ __forceinline__ int brargmax(float v, int idx, float* sw, int* si) {
    int t = threadIdx.x;
    #pragma unroll
    for (int o = 16; o > 0; o >>= 1) {
        float vo = __shfl_down_sync(FULLMASK, v, o);
        int   io = __shfl_down_sync(FULLMASK, idx, o);
        if (vo > v || (vo == v && io < idx)) { v = vo; idx = io; }
    }
    if ((t & 31) == 0) { sw[t >> 5] = v; si[t >> 5] = idx; }
    __syncthreads();
    if (t < 32) {
        float x = (t < 12) ? sw[t] : -INFINITY;
        int   i = (t < 12) ? si[t] : 0x7fffffff;
        #pragma unroll
        for (int o = 16; o > 0; o >>= 1) {
            float vo = __shfl_down_sync(FULLMASK, x, o);
            int   io = __shfl_down_sync(FULLMASK, i, o);
            if (vo > x || (vo == x && io < i)) { x = vo; i = io; }
        }
        if (t == 0) si[0] = i;
    }
    __syncthreads();
    int r = si[0];
    __syncthreads();
    return r;
}

// ================= kernel 1: shift/argmax/attn -> x_ele + denom partials =================
__global__ __launch_bounds__(384) void k_xele(const float* __restrict__ x,
                                              const float* __restrict__ y) {
    int row = blockIdx.x;
    int t = threadIdx.x;
    __shared__ __align__(16) float xp[1152];   // zero-padded: xp[i] = x[i-383]
    __shared__ __align__(16) float ys[Dk];
    __shared__ float xa[Dk];
    __shared__ float PS[Dk + 1];
    __shared__ float4 dpart[384];
    __shared__ float sw[12];
    __shared__ int   si[12];

    const float* xr = x + (size_t)row * Dk;
    const float* yr = y + (size_t)row * Dk;
    xp[t] = 0.f; xp[t + 384] = 0.f; xp[t + 768] = 0.f;
    float yv_t = yr[t];
    ys[t] = yv_t;
    __syncthreads();
    float xv_t = xr[t];
    xp[PADk + t] = xv_t;

    // prefix sums of x^2 : PS[u] = sum_{v<u} x[v]^2
    {
        float x2 = xv_t * xv_t;
        float incl = x2;
        #pragma unroll
        for (int o = 1; o < 32; o <<= 1) {
            float vv = __shfl_up_sync(FULLMASK, incl, o);
            if ((t & 31) >= o) incl += vv;
        }
        if ((t & 31) == 31) sw[t >> 5] = incl;
        __syncthreads();
        if (t < 32) {
            float wv = (t < 12) ? sw[t] : 0.f;
            float wi = wv;
            #pragma unroll
            for (int o = 1; o < 32; o <<= 1) {
                float vv = __shfl_up_sync(FULLMASK, wi, o);
                if (t >= o) wi += vv;
            }
            if (t < 12) sw[t] = wi - wv;   // exclusive warp offsets
        }
        __syncthreads();
        PS[t + 1] = incl + sw[t >> 5];
        if (t == 0) PS[0] = 0.f;
        __syncthreads();
    }

    float qn = sqrtf(brsum(yv_t * yv_t, sw));
    float cn = brsum((yv_t != 0.0f) ? 1.f : 0.f, sw);
    if (t == 0) g_cnt[row] = cn;

    // shift phase: 192 quads (4 shifts each) x 2 u-range halves; all 384 threads busy
    int qd = t % 192, uh = t / 192;
    int s0 = 4 * qd;
    {
        float d0 = 0.f, d1 = 0.f, d2 = 0.f, d3 = 0.f;
        int ub = uh * 192;
        float4 cur = *(const float4*)&xp[s0 + ub];
        const float4* ys4 = (const float4*)ys;
        #pragma unroll 4
        for (int u = ub; u < ub + 192; u += 4) {
            float4 nxt = *(const float4*)&xp[s0 + u + 4];
            float4 yv = ys4[u >> 2];
            d0 += cur.x * yv.x + cur.y * yv.y + cur.z * yv.z + cur.w * yv.w;
            d1 += cur.y * yv.x + cur.z * yv.y + cur.w * yv.z + nxt.x * yv.w;
            d2 += cur.z * yv.x + cur.w * yv.y + nxt.x * yv.z + nxt.y * yv.w;
            d3 += cur.w * yv.x + nxt.x * yv.y + nxt.y * yv.z + nxt.z * yv.w;
            cur = nxt;
        }
        float4 dq; dq.x = d0; dq.y = d1; dq.z = d2; dq.w = d3;
        dpart[t] = dq;
    }
    __syncthreads();

    float bv = -INFINITY; int bi = 0x7fffffff;
    if (t < 192) {
        float4 pa = dpart[t], pb = dpart[t + 192];
        float dots[4] = { pa.x + pb.x, pa.y + pb.y, pa.z + pb.z, pa.w + pb.w };
        #pragma unroll
        for (int q = 0; q < 4; ++q) {
            int s = s0 + q;
            if (s < Sk) {
                int hi = (s < Dk - 1 ? s : Dk - 1) + 1;
                int lo = (s - PADk > 0) ? (s - PADk) : 0;
                float ss = PS[hi] - PS[lo];
                float sim = dots[q] / (qn * sqrtf(ss) + EPSk);
                if (isnan(sim)) sim = 0.f;
                if (sim > bv) { bv = sim; bi = s; }   // ascending q keeps first index on tie
            }
        }
    }
    int theta = brargmax(bv, bi, sw, si);

    float v = xp[t + theta];
    float no = brsum(v * v, sw);
    float dn = sqrtf(no) * qn + EPSk;

    float z = (v * yv_t / dn) / TEMPERk;
    float m = brmax(z, sw);
    float e = expf(z - m);
    float ssum = brsum(e, sw);
    xa[t] = v * e / ssum;
    __syncthreads();

    int shift = theta - PADk;
    int u = t - shift;
    g_xele[(size_t)row * Dk + t] = (u >= 0 && u < Dk) ? xa[u] : 0.f;
    GDC_LAUNCH();
}

// ================= kernel 2: h = x_ele @ W_enc + b_enc =================
// grid 256 = 32 rowgroups(8 rows) x 8 colgroups(128 cols), 128 threads, 1 col/thread
__global__ __launch_bounds__(128) void k_enc(const float* __restrict__ We,
                                             const float* __restrict__ be) {
    int rg = blockIdx.x >> 3;
    int cg = blockIdx.x & 7;
    int t  = threadIdx.x;
    int col = cg * 128 + t;
    __shared__ __align__(16) float xs[8 * Dk];
    float b = be[col];           // independent of producer output
    GDC_WAIT();                  // g_xele must be complete past this point
    for (int i = t; i < 8 * Dk; i += 128) xs[i] = g_xele[(size_t)rg * 8 * Dk + i];
    __syncthreads();

    float acc[8];
    #pragma unroll
    for (int r = 0; r < 8; ++r) acc[r] = b;

    for (int k = 0; k < Dk; k += 4) {
        float w0 = We[(size_t)(k + 0) * Hk + col];
        float w1 = We[(size_t)(k + 1) * Hk + col];
        float w2 = We[(size_t)(k + 2) * Hk + col];
        float w3 = We[(size_t)(k + 3) * Hk + col];
        #pragma unroll
        for (int r = 0; r < 8; ++r) {
            float4 xv = *(const float4*)&xs[r * Dk + k];
            acc[r] += xv.x * w0;
            acc[r] += xv.y * w1;
            acc[r] += xv.z * w2;
            acc[r] += xv.w * w3;
        }
    }
    #pragma unroll
    for (int r = 0; r < 8; ++r)
        g_h[(size_t)(rg * 8 + r) * Hk + col] = acc[r];
    GDC_LAUNCH();
}

// ===== kernel 3 (fused): 4x top-256 (radix + shortcut) -> union decode -> loss =====
// one block per row, 384 threads  (R6/R9-proven structure)
__global__ __launch_bounds__(384) void k_seldec(const float* __restrict__ Wd,
                                                const float* __restrict__ bd,
                                                const float* __restrict__ x,
                                                const float* __restrict__ y,
                                                float* __restrict__ out,
                                                float* __restrict__ losses) {
    int row = blockIdx.x;
    int t = threadIdx.x;
    int lane = t & 31;

    __shared__ float    hs[Hk];
    __shared__ unsigned kv[Hk];
    __shared__ int      selhist[Hk];
    __shared__ int      sil[Hk];          // union row offsets (j*Dk)
    __shared__ float4   svl[Hk];          // per-union values for 4 iters
    __shared__ int      cnt[256];
    __shared__ int      sc[256];
    __shared__ float4   s4[12];
    __shared__ unsigned sh_prefix;
    __shared__ int      sh_k, sh_done, sh_ngnm, sh_U, slast;

    const unsigned MASKKEY = fkey(MASKVAL);

    GDC_WAIT();                 // g_h must be complete past this point
    const float* hr = g_h + (size_t)row * Hk;
    if (t < 256) {
        float4 h4 = *(const float4*)&hr[t * 4];
        hs[t*4+0] = h4.x; hs[t*4+1] = h4.y; hs[t*4+2] = h4.z; hs[t*4+3] = h4.w;
        kv[t*4+0] = fkey(h4.x); kv[t*4+1] = fkey(h4.y);
        kv[t*4+2] = fkey(h4.z); kv[t*4+3] = fkey(h4.w);
        selhist[t*4+0] = 0; selhist[t*4+1] = 0; selhist[t*4+2] = 0; selhist[t*4+3] = 0;
    }
    __syncthreads();

    // ---- 4 dependent top-k selections ----
    for (int it = 0; it < NITER; ++it) {
        unsigned Tkey; int k; unsigned pmaskF;
        int shortcut = 0;

        if (it > 0) {
            int packed = 0;
            if (t < 256) {
                int ng = 0, nm = 0;
                #pragma unroll
                for (int q = 0; q < 4; ++q) {
                    unsigned u = kv[t * 4 + q];
                    ng += (u > MASKKEY);
                    nm += (u == MASKKEY);
                }
                packed = (ng << 16) | nm;
            }
            #pragma unroll
            for (int o = 16; o > 0; o >>= 1) packed += __shfl_down_sync(FULLMASK, packed, o);
            if (lane == 0) sc[t >> 5] = packed;
            __syncthreads();
            if (t < 32) {
                int v = (t < 8) ? sc[t] : 0;
                #pragma unroll
                for (int o = 4; o > 0; o >>= 1) v += __shfl_down_sync(FULLMASK, v, o);
                if (t == 0) sh_ngnm = v;
            }
            __syncthreads();
            int ngT = sh_ngnm >> 16, nmT = sh_ngnm & 0xffff;
            if (ngT <= Ck && Ck <= ngT + nmT) {
                Tkey = MASKKEY; k = Ck - ngT; pmaskF = FULLMASK;
                shortcut = 1;
            }
            __syncthreads();
        }

        if (!shortcut) {
            if (t == 0) { sh_prefix = 0; sh_k = Ck; sh_done = 0; }
            __syncthreads();
            unsigned pmask = 0;
            for (int sb = 24; sb >= 0; sb -= 8) {
                if (sh_done) break;
                unsigned prefix = sh_prefix;
                if (t < 256) cnt[t] = 0;
                __syncthreads();
                #pragma unroll
                for (int ch = 0; ch < 3; ++ch) {
                    int i = t + ch * 384;
                    int bucket = -1;
                    if (i < Hk) {
                        unsigned u = kv[i];
                        if ((u & pmask) == prefix) bucket = (int)((u >> sb) & 0xffu);
                    }
                    unsigned same = __match_any_sync(FULLMASK, bucket);
                    if (bucket >= 0 && lane == (__ffs(same) - 1))
                        atomicAdd(&cnt[bucket], __popc(same));
                }
                __syncthreads();
                if (t < 32) {
                    int kk = sh_k;
                    int base = t * 8;
                    int c[8], s[8];
                    #pragma unroll
                    for (int q = 0; q < 8; ++q) c[q] = cnt[base + q];
                    s[7] = c[7];
                    #pragma unroll
                    for (int q = 6; q >= 0; --q) s[q] = s[q + 1] + c[q];
                    int tot = s[0];
                    int suf = tot;
                    #pragma unroll
                    for (int o = 1; o < 32; o <<= 1) {
                        int vv = __shfl_down_sync(FULLMASK, suf, o);
                        if (t + o < 32) suf += vv;
                    }
                    int basev = suf - tot;   // suffix over lanes > t
                    #pragma unroll
                    for (int q = 0; q < 8; ++q) {
                        int sq = basev + s[q];
                        int sn = (q < 7) ? basev + s[q + 1] : basev;
                        if (sq >= kk && sn < kk) {
                            sh_prefix = prefix | ((unsigned)(base + q) << sb);
                            sh_k = kk - sn;
                            if (sq == kk) sh_done = 1;
                        }
                    }
                }
                pmask |= (0xffu << sb);
                __syncthreads();
            }
            Tkey = sh_prefix; k = sh_k; pmaskF = pmask;
        }

        // tie-break by ascending index; thread t<256 owns elems [4t, 4t+4)
        int eq[4], gt_[4]; int eqc = 0;
        if (t < 256) {
            #pragma unroll
            for (int q = 0; q < 4; ++q) {
                unsigned u = kv[t * 4 + q] & pmaskF;
                eq[q]  = (u == Tkey);
                gt_[q] = (u >  Tkey);
                eqc += eq[q];
            }
            sc[t] = eqc;
        }
        __syncthreads();
        if (t < 32) {
            int base = t * 8;
            int v[8], inc[8];
            int run = 0;
            #pragma unroll
            for (int q = 0; q < 8; ++q) { v[q] = sc[base + q]; run += v[q]; inc[q] = run; }
            int tot = run, pre = tot;
            #pragma unroll
            for (int o = 1; o < 32; o <<= 1) {
                int vv = __shfl_up_sync(FULLMASK, pre, o);
                if (t >= o) pre += vv;
            }
            int basev = pre - tot;
            #pragma unroll
            for (int q = 0; q < 8; ++q) sc[base + q] = basev + inc[q] - v[q];
        }
        __syncthreads();
        if (t < 256) {
            int eqbase = sc[t];
            int le = 0;
            #pragma unroll
            for (int q = 0; q < 4; ++q) {
                int j = t * 4 + q;
                int sel = gt_[q] || (eq[q] && (eqbase + le) < k);
                le += eq[q];
                if (sel) { selhist[j] |= (1 << it); kv[j] = MASKKEY; }
            }
        }
        __syncthreads();
    }

    // ---- union compaction + per-iter value build (in smem) ----
    int uc = 0;
    if (t < 256) {
        #pragma unroll
        for (int q = 0; q < 4; ++q) uc += (selhist[t * 4 + q] != 0);
        sc[t] = uc;
    }
    __syncthreads();
    if (t < 32) {
        int base = t * 8;
        int v[8], inc[8];
        int run = 0;
        #pragma unroll
        for (int q = 0; q < 8; ++q) { v[q] = sc[base + q]; run += v[q]; inc[q] = run; }
        int tot = run, pre = tot;
        #pragma unroll
        for (int o = 1; o < 32; o <<= 1) {
            int vv = __shfl_up_sync(FULLMASK, pre, o);
            if (t >= o) pre += vv;
        }
        int basev = pre - tot;
        #pragma unroll
        for (int q = 0; q < 8; ++q) sc[base + q] = basev + inc[q] - v[q];
        if (t == 31) sh_U = basev + inc[7];
    }
    __syncthreads();
    if (t < 256) {
        int p = sc[t];
        #pragma unroll
        for (int q = 0; q < 4; ++q) {
            int j = t * 4 + q;
            int s = selhist[j];
            if (s) {
                float hv_ = hs[j];
                float4 v;
                v.x = (s & 1) ?  hv_ : 0.f;
                v.y = (s & 2) ? ((s & 1) ? MASKVAL : hv_) : 0.f;
                v.z = (s & 4) ? ((s & 3) ? MASKVAL : hv_) : 0.f;
                v.w = (s & 8) ? ((s & 7) ? MASKVAL : hv_) : 0.f;
                sil[p] = j * Dk;
                svl[p] = v;
                ++p;
            }
        }
    }
    __syncthreads();
    int U = sh_U;
    int Upad = (U + 7) & ~7;
    if (t < Upad - U) {
        float4 z; z.x = z.y = z.z = z.w = 0.f;
        sil[U + t] = 0;
        svl[U + t] = z;
    }
    __syncthreads();

    // ---- decode: thread t owns output column t for all 4 iters; unroll 8 ----
    float bdt = bd[t];
    float a0 = bdt, a1 = bdt, a2 = bdt, a3 = bdt;
    const float* Wt = Wd + t;
    for (int i = 0; i < Upad; i += 8) {
        int j0 = sil[i],   j1 = sil[i+1], j2 = sil[i+2], j3 = sil[i+3];
        int j4 = sil[i+4], j5 = sil[i+5], j6 = sil[i+6], j7 = sil[i+7];
        float w0 = Wt[j0], w1 = Wt[j1], w2 = Wt[j2], w3 = Wt[j3];
        float w4 = Wt[j4], w5 = Wt[j5], w6 = Wt[j6], w7 = Wt[j7];
        float4 v0 = svl[i],   v1 = svl[i+1], v2 = svl[i+2], v3 = svl[i+3];
        float4 v4 = svl[i+4], v5 = svl[i+5], v6 = svl[i+6], v7 = svl[i+7];
        a0 += v0.x * w0; a1 += v0.y * w0; a2 += v0.z * w0; a3 += v0.w * w0;
        a0 += v1.x * w1; a1 += v1.y * w1; a2 += v1.z * w1; a3 += v1.w * w1;
        a0 += v2.x * w2; a1 += v2.y * w2; a2 += v2.z * w2; a3 += v2.w * w2;
        a0 += v3.x * w3; a1 += v3.y * w3; a2 += v3.z * w3; a3 += v3.w * w3;
        a0 += v4.x * w4; a1 += v4.y * w4; a2 += v4.z * w4; a3 += v4.w * w4;
        a0 += v5.x * w5; a1 += v5.y * w5; a2 += v5.z * w5; a3 += v5.w * w5;
        a0 += v6.x * w6; a1 += v6.y * w6; a2 += v6.z * w6; a3 += v6.w * w6;
        a0 += v7.x * w7; a1 += v7.y * w7; a2 += v7.z * w7; a3 += v7.w * w7;
    }

    // ---- outputs + masked-MSE partials ----
    float xv = x[(size_t)row * Dk + t];
    float yv = y[(size_t)row * Dk + t];
    out[((size_t)0 * Nk + row) * Dk + t] = a0;
    out[((size_t)1 * Nk + row) * Dk + t] = a1;
    out[((size_t)2 * Nk + row) * Dk + t] = a2;
    out[((size_t)3 * Nk + row) * Dk + t] = a3;

    float4 d;
    if (yv != 0.0f) {
        float e0 = a0 - xv, e1 = a1 - xv, e2 = a2 - xv, e3 = a3 - xv;
        d.x = e0 * e0; d.y = e1 * e1; d.z = e2 * e2; d.w = e3 * e3;
    } else {
        d.x = d.y = d.z = d.w = 0.f;
    }
    #pragma unroll
    for (int o = 16; o > 0; o >>= 1) {
        d.x += __shfl_down_sync(FULLMASK, d.x, o);
        d.y += __shfl_down_sync(FULLMASK, d.y, o);
        d.z += __shfl_down_sync(FULLMASK, d.z, o);
        d.w += __shfl_down_sync(FULLMASK, d.w, o);
    }
    if (lane == 0) s4[t >> 5] = d;
    __syncthreads();
    if (t < 32) {
        float4 v;
        if (t < 12) v = s4[t];
        else { v.x = v.y = v.z = v.w = 0.f; }
        #pragma unroll
        for (int o = 16; o > 0; o >>= 1) {
            v.x += __shfl_down_sync(FULLMASK, v.x, o);
            v.y += __shfl_down_sync(FULLMASK, v.y, o);
            v.z += __shfl_down_sync(FULLMASK, v.z, o);
            v.w += __shfl_down_sync(FULLMASK, v.w, o);
        }
        if (t == 0) {
            g_partial[0 * Nk + row] = v.x;
            g_partial[1 * Nk + row] = v.y;
            g_partial[2 * Nk + row] = v.z;
            g_partial[3 * Nk + row] = v.w;
        }
    }
    __threadfence();
    if (t == 0) slast = (atomicAdd(&g_ctr, 1) == Nk - 1);
    __syncthreads();

    if (slast) {
        __shared__ float s_num[4];
        __shared__ float s_den;
        if (t < 128) {
            int w = t >> 5, l = t & 31;
            float s = 0.f;
            for (int j = l; j < Nk; j += 32) s += ((volatile float*)g_partial)[w * Nk + j];
            #pragma unroll
            for (int o = 16; o > 0; o >>= 1) s += __shfl_down_sync(FULLMASK, s, o);
            if (l == 0) s_num[w] = s;
        } else if (t < 160) {
            int l = t - 128;
            float dsum = 0.f;
            for (int j = l; j < Nk; j += 32) dsum += g_cnt[j];
            #pragma unroll
            for (int o = 16; o > 0; o >>= 1) dsum += __shfl_down_sync(FULLMASK, dsum, o);
            if (l == 0) s_den = dsum;
        }
        __syncthreads();
        if (t < 4) losses[t] = s_num[t] / s_den;
        if (t == 0) g_ctr = 0;   // reset for next graph replay
    }
}

extern "C" void kernel_launch(void* const* d_in, const int* in_sizes, int n_in,
                              void* d_out, int out_size) {
    const float* x  = (const float*)d_in[0];
    const float* y  = (const float*)d_in[1];
    const float* We = (const float*)d_in[2];
    const float* be = (const float*)d_in[3];
    const float* Wd = (const float*)d_in[4];
    const float* bd = (const float*)d_in[5];
    float* out = (float*)d_out;
    float* losses = out + (out_size - NITER);

    k_xele<<<Nk, 384>>>(x, y);

    cudaLaunchAttribute attr[1];
    attr[0].id = cudaLaunchAttributeProgrammaticStreamSerialization;
    attr[0].val.programmaticStreamSerializationAllowed = 1;

    {
        cudaLaunchConfig_t cfg = {};
        cfg.gridDim = dim3(256, 1, 1);
        cfg.blockDim = dim3(128, 1, 1);
        cfg.dynamicSmemBytes = 0;
        cfg.stream = 0;
        cfg.attrs = attr;
        cfg.numAttrs = 1;
        cudaLaunchKernelEx(&cfg, k_enc, We, be);
    }
    {
        cudaLaunchConfig_t cfg = {};
        cfg.gridDim = dim3(Nk, 1, 1);
        cfg.blockDim = dim3(384, 1, 1);
        cfg.dynamicSmemBytes = 0;
        cfg.stream = 0;
        cfg.attrs = attr;
        cfg.numAttrs = 1;
        cudaLaunchKernelEx(&cfg, k_seldec, Wd, bd, x, y, out, losses);
    }
}